// round 2
// baseline (speedup 1.0000x reference)
#include <cuda_runtime.h>
#include <math.h>

#define HWD 512
#define HW2 (512*512)
#define NB 4
#define NCB 8
#define KS 41
#define KH 20

// ---------------- device scratch (allocation-free rule: __device__ globals) ----------------
__device__ float  d_u[NCB*KS];           // separable 1D MTF factors per band
__device__ double g_acc[3];              // [0]=spec numerator, [1]=spec mask sum, [2]=struct sum

__device__ float d_tmp_spec[NB*NCB*HWD*128]; // row-pass of spec conv at sub columns
__device__ float d_panrow [NB*HW2];
__device__ float d_panf   [NB*HW2];
__device__ float d_da_pan [NB*HW2];
__device__ float d_db_ms  [NB*NCB*HW2];
__device__ float d_sab_t  [NB*NCB*HW2];
__device__ float d_sbb_t  [NB*NCB*HW2];
__device__ float d_saa_t  [NB*HW2];
__device__ float d_da_out [NB*NCB*HW2];
__device__ float d_db_pan [NB*HW2];
__device__ float d_sab_x  [NB*NCB*HW2];
__device__ float d_saa_x  [NB*NCB*HW2];
__device__ float d_sbb_x  [NB*HW2];

// ---------------- init: 1D kernel factors + zero accumulators ----------------
__global__ void k_init(const float* __restrict__ mtf) {
    int t = threadIdx.x;
    if (t < NCB*KS) {
        int c = t / KS, i = t - c*KS;
        // normalized 2D gaussian = u u^T  ->  u_i = sqrt(diag)
        d_u[t] = sqrtf(mtf[(size_t)c*KS*KS + i*KS + i]);
    }
    if (t == 0) { g_acc[0] = 0.0; g_acc[1] = 0.0; g_acc[2] = 0.0; }
}

// ---------------- spec branch: separable conv evaluated only at 2::4 sites ----------------
__global__ void k_spec_h(const float* __restrict__ outputs) {
    int idx = blockIdx.x*256 + threadIdx.x;   // NB*NCB*512*128
    if (idx >= NB*NCB*HWD*128) return;
    int jb = idx & 127;
    int i  = (idx >> 7) & 511;
    int c  = (idx >> 16) & 7;
    int b  =  idx >> 19;
    int j = 2 + 4*jb;
    const float* row = outputs + ((size_t)(b*NCB + c)*HWD + i)*HWD;
    const float* u = d_u + c*KS;
    float s = 0.f;
    #pragma unroll
    for (int t = 0; t < KS; t++) {
        int jj = j - KH + t;
        if (jj >= 0 && jj < HWD) s += u[t] * row[jj];
    }
    d_tmp_spec[idx] = s;
}

__global__ void k_spec_v(const float* __restrict__ labels, const float* __restrict__ mask) {
    __shared__ double sd[256];
    int idx = blockIdx.x*256 + threadIdx.x;   // NB*NCB*128*128
    double num = 0.0, den = 0.0;
    if (idx < NB*NCB*128*128) {
        int bb = idx & 127;
        int a  = (idx >> 7) & 127;
        int c  = (idx >> 14) & 7;
        int b  =  idx >> 17;
        int i = 2 + 4*a, j = 2 + 4*bb;
        const float* u = d_u + c*KS;
        float x = 0.f;
        #pragma unroll
        for (int s = 0; s < KS; s++) {
            int ii = i - KH + s;
            if (ii >= 0 && ii < HWD)
                x += u[s] * d_tmp_spec[((size_t)(b*NCB + c)*HWD + ii)*128 + bb];
        }
        float y = labels[((size_t)(b*9 + c)*HWD + i)*HWD + j];
        float m = mask[((size_t)c*HWD + i)*HWD + j];
        num = (double)(m * fabsf(x - y));
        den = (double)m;
    }
    int t = threadIdx.x;
    sd[t] = num; __syncthreads();
    for (int s = 128; s > 0; s >>= 1) { if (t < s) sd[t] += sd[t+s]; __syncthreads(); }
    double rnum = sd[0]; __syncthreads();
    sd[t] = den; __syncthreads();
    for (int s = 128; s > 0; s >>= 1) { if (t < s) sd[t] += sd[t+s]; __syncthreads(); }
    if (t == 0) { atomicAdd(&g_acc[0], rnum); atomicAdd(&g_acc[1], sd[0]); }
}

// ---------------- pan low-pass (edge padding), separable ----------------
__global__ void k_pan_row(const float* __restrict__ inp) {
    int idx = blockIdx.x*256 + threadIdx.x;   // NB*HW2
    if (idx >= NB*HW2) return;
    int j = idx & 511;
    int i = (idx >> 9) & 511;
    int b =  idx >> 18;
    const float* row = inp + ((size_t)(b*9 + 8)*HWD + i)*HWD;
    const float* u = d_u;  // band 0
    float s = 0.f;
    #pragma unroll
    for (int t = 0; t < KS; t++) {
        int jj = j - KH + t;
        jj = jj < 0 ? 0 : (jj > HWD-1 ? HWD-1 : jj);
        s += u[t] * row[jj];
    }
    d_panrow[idx] = s;
}

__global__ void k_pan_col() {
    int idx = blockIdx.x*256 + threadIdx.x;
    if (idx >= NB*HW2) return;
    int j = idx & 511;
    int i = (idx >> 9) & 511;
    int b =  idx >> 18;
    const float* u = d_u;
    float s = 0.f;
    #pragma unroll
    for (int t = 0; t < KS; t++) {
        int ii = i - KH + t;
        ii = ii < 0 ? 0 : (ii > HWD-1 ? HWD-1 : ii);
        s += u[t] * d_panrow[((size_t)b*HWD + ii)*HWD + j];
    }
    d_panf[idx] = s;
}

// ---------------- fused tiled box kernels ----------------
// boxsum window: rows i-W+1..i+W, cols j-W+1..j+W (2W x 2W), zero outside.

template<int W>
__global__ void k_boxdb(float* __restrict__ out, const float* __restrict__ in,
                        int inC, int chanOff, int nC) {
    constexpr int TS = 31 + 2*W;
    __shared__ float raw[TS][TS+1];
    __shared__ float hs[TS][32];
    int p = blockIdx.z;
    int b = p / nC, c = p - b*nC;
    const float* ip = in + (size_t)(b*inC + chanOff + c)*HW2;
    float* op = out + (size_t)p*HW2;
    int ty0 = blockIdx.y*32 - (W-1);
    int tx0 = blockIdx.x*32 - (W-1);
    int tid = threadIdx.y*32 + threadIdx.x;
    for (int idx = tid; idx < TS*TS; idx += 256) {
        int r = idx / TS, q = idx - r*TS;
        int gi = ty0 + r, gj = tx0 + q;
        raw[r][q] = (gi >= 0 && gi < HWD && gj >= 0 && gj < HWD) ? ip[gi*HWD + gj] : 0.f;
    }
    __syncthreads();
    for (int r = threadIdx.y; r < TS; r += 8) {
        float s = 0.f;
        #pragma unroll
        for (int q = 0; q < 2*W; q++) s += raw[r][threadIdx.x + q];
        hs[r][threadIdx.x] = s;
    }
    __syncthreads();
    const float invn = 1.0f / (4.0f*W*W);
    int oj = blockIdx.x*32 + threadIdx.x;
    #pragma unroll
    for (int k = 0; k < 4; k++) {
        int ly = threadIdx.y + 8*k;
        int oi = blockIdx.y*32 + ly;
        float s = 0.f;
        #pragma unroll
        for (int r = 0; r < 2*W; r++) s += hs[ly + r][threadIdx.x];
        float center = raw[ly + W - 1][threadIdx.x + W - 1];
        op[oi*HWD + oj] = center - s*invn;
    }
}

template<int W>
__global__ void k_boxprod(float* __restrict__ out, const float* __restrict__ A,
                          const float* __restrict__ Bf, int aNC, int bNC) {
    constexpr int TS = 31 + 2*W;
    __shared__ float raw[TS][TS+1];
    __shared__ float hs[TS][32];
    int nC = aNC > bNC ? aNC : bNC;
    int p = blockIdx.z;
    int b = p / nC, c = p - b*nC;
    const float* ap = A  + (size_t)(b*aNC + (aNC == nC ? c : 0))*HW2;
    const float* bp = Bf + (size_t)(b*bNC + (bNC == nC ? c : 0))*HW2;
    float* op = out + (size_t)p*HW2;
    int ty0 = blockIdx.y*32 - (W-1);
    int tx0 = blockIdx.x*32 - (W-1);
    int tid = threadIdx.y*32 + threadIdx.x;
    for (int idx = tid; idx < TS*TS; idx += 256) {
        int r = idx / TS, q = idx - r*TS;
        int gi = ty0 + r, gj = tx0 + q;
        float v = 0.f;
        if (gi >= 0 && gi < HWD && gj >= 0 && gj < HWD) {
            int o = gi*HWD + gj;
            v = ap[o] * bp[o];
        }
        raw[r][q] = v;
    }
    __syncthreads();
    for (int r = threadIdx.y; r < TS; r += 8) {
        float s = 0.f;
        #pragma unroll
        for (int q = 0; q < 2*W; q++) s += raw[r][threadIdx.x + q];
        hs[r][threadIdx.x] = s;
    }
    __syncthreads();
    int oj = blockIdx.x*32 + threadIdx.x;
    #pragma unroll
    for (int k = 0; k < 4; k++) {
        int ly = threadIdx.y + 8*k;
        int oi = blockIdx.y*32 + ly;
        float s = 0.f;
        #pragma unroll
        for (int r = 0; r < 2*W; r++) s += hs[ly + r][threadIdx.x];
        op[oi*HWD + oj] = s;
    }
}

// ---------------- final structural combine + reduction ----------------
__global__ void k_struct() {
    __shared__ double sd[256];
    int idx = blockIdx.x*256 + threadIdx.x;   // NB*NCB*HW2 = 8388608
    double v = 0.0;
    if (idx < NB*NCB*HW2) {
        int pos = idx & (HW2 - 1);
        int p   = idx >> 18;   // HW2 = 2^18
        int b   = p >> 3;
        float sab_t = d_sab_t[idx];
        float sbb_t = d_sbb_t[idx];
        float saa_t = d_saa_t[(size_t)b*HW2 + pos];
        float thr = 1.f - sab_t / (sqrtf(saa_t * sbb_t) + 1e-20f);
        float sab_x = d_sab_x[idx];
        float saa_x = d_saa_x[idx];
        float sbb_x = d_sbb_x[(size_t)b*HW2 + pos];
        float xc = sab_x / (sqrtf(saa_x * sbb_x) + 1e-20f);
        xc = fmaxf(xc, -1.f);
        float X = 1.f - xc;
        v = (X > thr) ? (double)X : 0.0;
    }
    int t = threadIdx.x;
    sd[t] = v; __syncthreads();
    for (int s = 128; s > 0; s >>= 1) { if (t < s) sd[t] += sd[t+s]; __syncthreads(); }
    if (t == 0) atomicAdd(&g_acc[2], sd[0]);
}

__global__ void k_write(float* __restrict__ out) {
    double l_spec   = g_acc[0] / g_acc[1];
    double l_struct = g_acc[2] / (double)((size_t)NB*NCB*HW2);
    out[0] = (float)(l_spec + 0.25 * l_struct);
}

// ---------------- host launcher ----------------
extern "C" void kernel_launch(void* const* d_in, const int* in_sizes, int n_in,
                              void* d_out, int out_size) {
    const float* outputs = (const float*)d_in[0];
    const float* labels  = (const float*)d_in[1];
    const float* inp     = (const float*)d_in[2];
    const float* mtf     = (const float*)d_in[3];
    const float* mask    = (const float*)d_in[4];
    float* out = (float*)d_out;

    float *p_panf, *p_da_pan, *p_db_ms, *p_sab_t, *p_sbb_t, *p_saa_t;
    float *p_da_out, *p_db_pan, *p_sab_x, *p_saa_x, *p_sbb_x;
    cudaGetSymbolAddress((void**)&p_panf,   d_panf);
    cudaGetSymbolAddress((void**)&p_da_pan, d_da_pan);
    cudaGetSymbolAddress((void**)&p_db_ms,  d_db_ms);
    cudaGetSymbolAddress((void**)&p_sab_t,  d_sab_t);
    cudaGetSymbolAddress((void**)&p_sbb_t,  d_sbb_t);
    cudaGetSymbolAddress((void**)&p_saa_t,  d_saa_t);
    cudaGetSymbolAddress((void**)&p_da_out, d_da_out);
    cudaGetSymbolAddress((void**)&p_db_pan, d_db_pan);
    cudaGetSymbolAddress((void**)&p_sab_x,  d_sab_x);
    cudaGetSymbolAddress((void**)&p_saa_x,  d_saa_x);
    cudaGetSymbolAddress((void**)&p_sbb_x,  d_sbb_x);

    dim3 bt(32, 8);

    k_init<<<1, 512>>>(mtf);

    // spec branch
    k_spec_h<<<(NB*NCB*HWD*128)/256, 256>>>(outputs);
    k_spec_v<<<(NB*NCB*128*128)/256, 256>>>(labels, mask);

    // pan low-pass (edge-padded, separable)
    k_pan_row<<<(NB*HW2)/256, 256>>>(inp);
    k_pan_col<<<(NB*HW2)/256, 256>>>();

    // thr branch (w=8)
    k_boxdb<8><<<dim3(16,16,NB),      bt>>>(p_da_pan, p_panf, 1, 0, 1);
    k_boxdb<8><<<dim3(16,16,NB*NCB),  bt>>>(p_db_ms,  inp,    9, 0, NCB);
    k_boxprod<8><<<dim3(16,16,NB*NCB), bt>>>(p_sab_t, p_da_pan, p_db_ms, 1, NCB);
    k_boxprod<8><<<dim3(16,16,NB*NCB), bt>>>(p_sbb_t, p_db_ms,  p_db_ms, NCB, NCB);
    k_boxprod<8><<<dim3(16,16,NB),     bt>>>(p_saa_t, p_da_pan, p_da_pan, 1, 1);

    // Xc branch (w=2)
    k_boxdb<2><<<dim3(16,16,NB*NCB), bt>>>(p_da_out, outputs, NCB, 0, NCB);
    k_boxdb<2><<<dim3(16,16,NB),     bt>>>(p_db_pan, labels,  9,   8, 1);
    k_boxprod<2><<<dim3(16,16,NB*NCB), bt>>>(p_sab_x, p_da_out, p_db_pan, NCB, 1);
    k_boxprod<2><<<dim3(16,16,NB*NCB), bt>>>(p_saa_x, p_da_out, p_da_out, NCB, NCB);
    k_boxprod<2><<<dim3(16,16,NB),     bt>>>(p_sbb_x, p_db_pan, p_db_pan, 1, 1);

    // combine + reduce
    k_struct<<<(NB*NCB*HW2)/256, 256>>>();
    k_write<<<1, 1>>>(out);
}

// round 3
// speedup vs baseline: 1.4803x; 1.4803x over previous
#include <cuda_runtime.h>
#include <math.h>

#define HWD 512
#define HW2 (512*512)
#define NB 4
#define NCB 8
#define KS 41
#define KH 20

// ---------------- device scratch (allocation-free rule: __device__ globals) ----------------
__device__ float  d_u[NCB*KS];
__device__ double g_acc[3];              // [0]=spec num, [1]=spec mask sum, [2]=struct sum

__device__ float d_tmp_spec[NB*NCB*HWD*128];
__device__ float d_panrow [NB*HW2];
__device__ float d_panf   [NB*HW2];
__device__ float d_da_pan [NB*HW2];
__device__ float d_db_ms  [NB*NCB*HW2];
__device__ float d_saa_t  [NB*HW2];
__device__ float d_da_out [NB*NCB*HW2];
__device__ float d_db_pan [NB*HW2];
__device__ float d_sbb_x  [NB*HW2];

// ---------------- init ----------------
__global__ void k_init(const float* __restrict__ mtf) {
    int t = threadIdx.x;
    if (t < NCB*KS) {
        int c = t / KS, i = t - c*KS;
        d_u[t] = sqrtf(mtf[(size_t)c*KS*KS + i*KS + i]);  // k = u u^T
    }
    if (t == 0) { g_acc[0] = 0.0; g_acc[1] = 0.0; g_acc[2] = 0.0; }
}

// ---------------- spec branch: separable conv at 2::4 sites only ----------------
__global__ void k_spec_h(const float* __restrict__ outputs) {
    int idx = blockIdx.x*256 + threadIdx.x;   // NB*NCB*512*128
    if (idx >= NB*NCB*HWD*128) return;
    int jb = idx & 127;
    int i  = (idx >> 7) & 511;
    int c  = (idx >> 16) & 7;
    int b  =  idx >> 19;
    int j = 2 + 4*jb;
    const float* row = outputs + ((size_t)(b*NCB + c)*HWD + i)*HWD;
    const float* u = d_u + c*KS;
    float s = 0.f;
    if (j >= KH && j < HWD - KH) {
        const float* rp = row + j - KH;
        #pragma unroll
        for (int t = 0; t < KS; t++) s += u[t] * rp[t];
    } else {
        #pragma unroll
        for (int t = 0; t < KS; t++) {
            int jj = j - KH + t;
            if (jj >= 0 && jj < HWD) s += u[t] * row[jj];
        }
    }
    d_tmp_spec[idx] = s;
}

__global__ void k_spec_v(const float* __restrict__ labels, const float* __restrict__ mask) {
    __shared__ double sd[256];
    int idx = blockIdx.x*256 + threadIdx.x;   // NB*NCB*128*128
    double num = 0.0, den = 0.0;
    if (idx < NB*NCB*128*128) {
        int bb = idx & 127;
        int a  = (idx >> 7) & 127;
        int c  = (idx >> 14) & 7;
        int b  =  idx >> 17;
        int i = 2 + 4*a, j = 2 + 4*bb;
        const float* u = d_u + c*KS;
        const float* col = d_tmp_spec + (size_t)(b*NCB + c)*HWD*128 + bb;
        float x = 0.f;
        if (i >= KH && i < HWD - KH) {
            const float* cp = col + (size_t)(i - KH)*128;
            #pragma unroll
            for (int s = 0; s < KS; s++) x += u[s] * cp[(size_t)s*128];
        } else {
            #pragma unroll
            for (int s = 0; s < KS; s++) {
                int ii = i - KH + s;
                if (ii >= 0 && ii < HWD) x += u[s] * col[(size_t)ii*128];
            }
        }
        float y = labels[((size_t)(b*9 + c)*HWD + i)*HWD + j];
        float m = mask[((size_t)c*HWD + i)*HWD + j];
        num = (double)(m * fabsf(x - y));
        den = (double)m;
    }
    int t = threadIdx.x;
    sd[t] = num; __syncthreads();
    for (int s = 128; s > 0; s >>= 1) { if (t < s) sd[t] += sd[t+s]; __syncthreads(); }
    double rnum = sd[0]; __syncthreads();
    sd[t] = den; __syncthreads();
    for (int s = 128; s > 0; s >>= 1) { if (t < s) sd[t] += sd[t+s]; __syncthreads(); }
    if (t == 0) { atomicAdd(&g_acc[0], rnum); atomicAdd(&g_acc[1], sd[0]); }
}

// ---------------- pan low-pass (edge padded), separable with interior fast path ----------------
__global__ void k_pan_row(const float* __restrict__ inp) {
    int idx = blockIdx.x*256 + threadIdx.x;
    if (idx >= NB*HW2) return;
    int j = idx & 511;
    int i = (idx >> 9) & 511;
    int b =  idx >> 18;
    const float* row = inp + ((size_t)(b*9 + 8)*HWD + i)*HWD;
    const float* u = d_u;
    float s = 0.f;
    if (j >= KH && j < HWD - KH) {
        const float* rp = row + j - KH;
        #pragma unroll
        for (int t = 0; t < KS; t++) s += u[t] * rp[t];
    } else {
        #pragma unroll
        for (int t = 0; t < KS; t++) {
            int jj = j - KH + t;
            jj = jj < 0 ? 0 : (jj > HWD-1 ? HWD-1 : jj);
            s += u[t] * row[jj];
        }
    }
    d_panrow[idx] = s;
}

__global__ void k_pan_col() {
    int idx = blockIdx.x*256 + threadIdx.x;
    if (idx >= NB*HW2) return;
    int j = idx & 511;
    int i = (idx >> 9) & 511;
    int b =  idx >> 18;
    const float* u = d_u;
    const float* col = d_panrow + (size_t)b*HW2 + j;
    float s = 0.f;
    if (i >= KH && i < HWD - KH) {
        const float* cp = col + (size_t)(i - KH)*HWD;
        #pragma unroll
        for (int t = 0; t < KS; t++) s += u[t] * cp[(size_t)t*HWD];
    } else {
        #pragma unroll
        for (int t = 0; t < KS; t++) {
            int ii = i - KH + t;
            ii = ii < 0 ? 0 : (ii > HWD-1 ? HWD-1 : ii);
            s += u[t] * col[(size_t)ii*HWD];
        }
    }
    d_panf[idx] = s;
}

// ---------------- boxdb: da = x - box2W(x)/n (incremental vertical) ----------------
template<int W>
__global__ void k_boxdb(float* __restrict__ out, const float* __restrict__ in,
                        int inC, int chanOff, int nC) {
    constexpr int TS = 31 + 2*W;
    __shared__ float raw[TS][TS+1];
    __shared__ float hs[TS][32];
    int p = blockIdx.z;
    int b = p / nC, c = p - b*nC;
    const float* ip = in + (size_t)(b*inC + chanOff + c)*HW2;
    float* op = out + (size_t)p*HW2;
    int y0 = blockIdx.y*32, x0 = blockIdx.x*32;
    int ty0 = y0 - (W-1), tx0 = x0 - (W-1);
    int tx = threadIdx.x, ty = threadIdx.y;
    int tid = ty*32 + tx;
    for (int idx = tid; idx < TS*TS; idx += 256) {
        int r = idx / TS, q = idx - r*TS;
        int gi = ty0 + r, gj = tx0 + q;
        raw[r][q] = ((unsigned)gi < HWD && (unsigned)gj < HWD) ? ip[gi*HWD + gj] : 0.f;
    }
    __syncthreads();
    for (int r = ty; r < TS; r += 8) {
        float s = 0.f;
        #pragma unroll
        for (int q = 0; q < 2*W; q++) s += raw[r][tx + q];
        hs[r][tx] = s;
    }
    __syncthreads();
    const float invn = 1.0f / (4.0f*W*W);
    int ly0 = ty*4;
    float s = 0.f;
    #pragma unroll
    for (int r = 0; r < 2*W; r++) s += hs[ly0 + r][tx];
    #pragma unroll
    for (int k = 0; k < 4; k++) {
        int ly = ly0 + k;
        op[(y0 + ly)*HWD + x0 + tx] = raw[ly + W - 1][tx + W - 1] - s*invn;
        if (k < 3) s += hs[ly + 2*W][tx] - hs[ly][tx];
    }
}

// ---------------- boxsq: out = box2W(A*A), per-b fields ----------------
template<int W>
__global__ void k_boxsq(float* __restrict__ out, const float* __restrict__ A) {
    constexpr int TS = 31 + 2*W;
    __shared__ float raw[TS][TS+1];
    __shared__ float hs[TS][32];
    int b = blockIdx.z;
    const float* ap = A + (size_t)b*HW2;
    float* op = out + (size_t)b*HW2;
    int y0 = blockIdx.y*32, x0 = blockIdx.x*32;
    int ty0 = y0 - (W-1), tx0 = x0 - (W-1);
    int tx = threadIdx.x, ty = threadIdx.y;
    int tid = ty*32 + tx;
    for (int idx = tid; idx < TS*TS; idx += 256) {
        int r = idx / TS, q = idx - r*TS;
        int gi = ty0 + r, gj = tx0 + q;
        float v = 0.f;
        if ((unsigned)gi < HWD && (unsigned)gj < HWD) { float a = ap[gi*HWD + gj]; v = a*a; }
        raw[r][q] = v;
    }
    __syncthreads();
    for (int r = ty; r < TS; r += 8) {
        float s = 0.f;
        #pragma unroll
        for (int q = 0; q < 2*W; q++) s += raw[r][tx + q];
        hs[r][tx] = s;
    }
    __syncthreads();
    int ly0 = ty*4;
    float s = 0.f;
    #pragma unroll
    for (int r = 0; r < 2*W; r++) s += hs[ly0 + r][tx];
    #pragma unroll
    for (int k = 0; k < 4; k++) {
        int ly = ly0 + k;
        op[(y0 + ly)*HWD + x0 + tx] = s;
        if (k < 3) s += hs[ly + 2*W][tx] - hs[ly][tx];
    }
}

// ---------------- mega-fused structural kernel ----------------
// Per 32x32 tile, per (b,c): computes thr (w=8 xcorr of pan_lp vs ms) and
// X (w=2 xcorr of outputs vs pan label), applies mask, block-reduces.
__global__ void k_fuse() {
    __shared__ float sm[7520];
    __shared__ double sd[256];
    int p = blockIdx.z;
    int b = p >> 3;
    int tx = threadIdx.x, ty = threadIdx.y;
    int tid = ty*32 + tx;
    int y0 = blockIdx.y*32, x0 = blockIdx.x*32;
    int ly0 = ty*4;

    // ---- phase 1: w=8 (thr) ----
    {
        float* rawA = sm;              // [47][48]  da_pan
        float* rawB = sm + 2256;       // [47][48]  db_ms
        float* hsAB = sm + 4512;       // [47][32]
        float* hsBB = sm + 6016;       // [47][32]
        const float* A = d_da_pan + (size_t)b*HW2;
        const float* B = d_db_ms  + (size_t)p*HW2;
        int ty0 = y0 - 7, tx0 = x0 - 7;
        for (int idx = tid; idx < 47*47; idx += 256) {
            int r = idx / 47, q = idx - r*47;
            int gi = ty0 + r, gj = tx0 + q;
            float va = 0.f, vb = 0.f;
            if ((unsigned)gi < HWD && (unsigned)gj < HWD) {
                int o = gi*HWD + gj;
                va = A[o]; vb = B[o];
            }
            rawA[r*48 + q] = va; rawB[r*48 + q] = vb;
        }
        __syncthreads();
        for (int r = ty; r < 47; r += 8) {
            float sa = 0.f, sb = 0.f;
            #pragma unroll
            for (int q = 0; q < 16; q++) {
                float a = rawA[r*48 + tx + q], bb = rawB[r*48 + tx + q];
                sa += a*bb; sb += bb*bb;
            }
            hsAB[r*32 + tx] = sa; hsBB[r*32 + tx] = sb;
        }
        __syncthreads();
    }
    float thrv[4];
    {
        float* hsAB = sm + 4512;
        float* hsBB = sm + 6016;
        const float* SAA = d_saa_t + (size_t)b*HW2;
        float sab = 0.f, sbb = 0.f;
        #pragma unroll
        for (int r = 0; r < 16; r++) { sab += hsAB[(ly0+r)*32 + tx]; sbb += hsBB[(ly0+r)*32 + tx]; }
        #pragma unroll
        for (int k = 0; k < 4; k++) {
            int oi = y0 + ly0 + k;
            float saa = SAA[oi*HWD + x0 + tx];
            thrv[k] = 1.f - sab / (sqrtf(saa*sbb) + 1e-20f);
            if (k < 3) {
                sab += hsAB[(ly0+16+k)*32 + tx] - hsAB[(ly0+k)*32 + tx];
                sbb += hsBB[(ly0+16+k)*32 + tx] - hsBB[(ly0+k)*32 + tx];
            }
        }
    }
    __syncthreads();

    // ---- phase 2: w=2 (X), reuse smem ----
    {
        float* rawC = sm;              // [35][36]  da_out
        float* rawD = sm + 1260;       // [35][36]  db_pan
        const float* C = d_da_out + (size_t)p*HW2;
        const float* D = d_db_pan + (size_t)b*HW2;
        int ty0 = y0 - 1, tx0 = x0 - 1;
        for (int idx = tid; idx < 35*35; idx += 256) {
            int r = idx / 35, q = idx - r*35;
            int gi = ty0 + r, gj = tx0 + q;
            float vc = 0.f, vd = 0.f;
            if ((unsigned)gi < HWD && (unsigned)gj < HWD) {
                int o = gi*HWD + gj;
                vc = C[o]; vd = D[o];
            }
            rawC[r*36 + q] = vc; rawD[r*36 + q] = vd;
        }
        __syncthreads();
        float* hsCD = sm + 2520;       // [35][32]
        float* hsCC = sm + 3640;       // [35][32]
        for (int r = ty; r < 35; r += 8) {
            float scd = 0.f, scc = 0.f;
            #pragma unroll
            for (int q = 0; q < 4; q++) {
                float cc = rawC[r*36 + tx + q], dd = rawD[r*36 + tx + q];
                scd += cc*dd; scc += cc*cc;
            }
            hsCD[r*32 + tx] = scd; hsCC[r*32 + tx] = scc;
        }
        __syncthreads();
        const float* SBB = d_sbb_x + (size_t)b*HW2;
        float scd = 0.f, scc = 0.f;
        #pragma unroll
        for (int r = 0; r < 4; r++) { scd += hsCD[(ly0+r)*32 + tx]; scc += hsCC[(ly0+r)*32 + tx]; }
        double acc = 0.0;
        #pragma unroll
        for (int k = 0; k < 4; k++) {
            int oi = y0 + ly0 + k;
            float sbbx = SBB[oi*HWD + x0 + tx];
            float xc = scd / (sqrtf(scc*sbbx) + 1e-20f);
            xc = fmaxf(xc, -1.f);
            float X = 1.f - xc;
            if (X > thrv[k]) acc += (double)X;
            if (k < 3) {
                scd += hsCD[(ly0+4+k)*32 + tx] - hsCD[(ly0+k)*32 + tx];
                scc += hsCC[(ly0+4+k)*32 + tx] - hsCC[(ly0+k)*32 + tx];
            }
        }
        sd[tid] = acc;
    }
    __syncthreads();
    for (int s = 128; s > 0; s >>= 1) { if (tid < s) sd[tid] += sd[tid+s]; __syncthreads(); }
    if (tid == 0) atomicAdd(&g_acc[2], sd[0]);
}

__global__ void k_write(float* __restrict__ out) {
    double l_spec   = g_acc[0] / g_acc[1];
    double l_struct = g_acc[2] / (double)((size_t)NB*NCB*HW2);
    out[0] = (float)(l_spec + 0.25 * l_struct);
}

// ---------------- host launcher ----------------
extern "C" void kernel_launch(void* const* d_in, const int* in_sizes, int n_in,
                              void* d_out, int out_size) {
    const float* outputs = (const float*)d_in[0];
    const float* labels  = (const float*)d_in[1];
    const float* inp     = (const float*)d_in[2];
    const float* mtf     = (const float*)d_in[3];
    const float* mask    = (const float*)d_in[4];
    float* out = (float*)d_out;

    float *p_panf, *p_da_pan, *p_db_ms, *p_saa_t, *p_da_out, *p_db_pan, *p_sbb_x;
    cudaGetSymbolAddress((void**)&p_panf,   d_panf);
    cudaGetSymbolAddress((void**)&p_da_pan, d_da_pan);
    cudaGetSymbolAddress((void**)&p_db_ms,  d_db_ms);
    cudaGetSymbolAddress((void**)&p_saa_t,  d_saa_t);
    cudaGetSymbolAddress((void**)&p_da_out, d_da_out);
    cudaGetSymbolAddress((void**)&p_db_pan, d_db_pan);
    cudaGetSymbolAddress((void**)&p_sbb_x,  d_sbb_x);

    dim3 bt(32, 8);

    k_init<<<1, 512>>>(mtf);

    // spec branch
    k_spec_h<<<(NB*NCB*HWD*128)/256, 256>>>(outputs);
    k_spec_v<<<(NB*NCB*128*128)/256, 256>>>(labels, mask);

    // pan low-pass
    k_pan_row<<<(NB*HW2)/256, 256>>>(inp);
    k_pan_col<<<(NB*HW2)/256, 256>>>();

    // da fields
    k_boxdb<8><<<dim3(16,16,NB),     bt>>>(p_da_pan, p_panf, 1, 0, 1);
    k_boxdb<8><<<dim3(16,16,NB*NCB), bt>>>(p_db_ms,  inp,    9, 0, NCB);
    k_boxdb<2><<<dim3(16,16,NB*NCB), bt>>>(p_da_out, outputs, NCB, 0, NCB);
    k_boxdb<2><<<dim3(16,16,NB),     bt>>>(p_db_pan, labels,  9,   8, 1);

    // per-b self-correlation fields
    k_boxsq<8><<<dim3(16,16,NB), bt>>>(p_saa_t, p_da_pan);
    k_boxsq<2><<<dim3(16,16,NB), bt>>>(p_sbb_x, p_db_pan);

    // fused structural combine + reduce
    k_fuse<<<dim3(16,16,NB*NCB), bt>>>();

    k_write<<<1, 1>>>(out);
}

// round 4
// speedup vs baseline: 1.5071x; 1.0182x over previous
#include <cuda_runtime.h>
#include <math.h>

#define HWD 512
#define HW2 (512*512)
#define NB 4
#define NCB 8
#define KS 41
#define KH 20

// ---------------- device scratch ----------------
__device__ float  d_u[NCB*KS];
__device__ double g_acc[3];              // [0]=spec num, [1]=spec mask sum, [2]=struct sum

__device__ float d_tmp_spec[NB*NCB*HWD*128];
__device__ float d_panrow [NB*HW2];
__device__ float d_panf   [NB*HW2];
__device__ float d_da_pan [NB*HW2];
__device__ float d_db_ms  [NB*NCB*HW2];
__device__ float d_saa_t  [NB*HW2];
__device__ float d_da_out [NB*NCB*HW2];
__device__ float d_db_pan [NB*HW2];
__device__ float d_sbb_x  [NB*HW2];

// ---------------- init ----------------
__global__ void k_init(const float* __restrict__ mtf) {
    int t = threadIdx.x;
    if (t < NCB*KS) {
        int c = t / KS, i = t - c*KS;
        d_u[t] = sqrtf(mtf[(size_t)c*KS*KS + i*KS + i]);  // k = u u^T
    }
    if (t == 0) { g_acc[0] = 0.0; g_acc[1] = 0.0; g_acc[2] = 0.0; }
}

// ---------------- spec branch: separable conv at 2::4 sites, 4 outputs/thread ----------------
__global__ void k_spec_h(const float* __restrict__ outputs) {
    int idx = blockIdx.x*256 + threadIdx.x;   // NB*NCB*512*32
    if (idx >= NB*NCB*HWD*32) return;
    int g  = idx & 31;
    int i  = (idx >> 5) & 511;
    int c  = (idx >> 14) & 7;
    int b  =  idx >> 17;
    const float* row = outputs + ((size_t)(b*NCB + c)*HWD + i)*HWD;
    const float* u = d_u + c*KS;
    float o0=0.f, o1=0.f, o2=0.f, o3=0.f;
    if (g >= 2 && g <= 29) {
        // outputs at j = 2+16g+4m, m=0..3; window [16g-18, 16g+34] = 53 floats
        const float* rp = row + 16*g - 18;
        float rb[53];
        #pragma unroll
        for (int t = 0; t < 53; t++) rb[t] = rp[t];
        #pragma unroll
        for (int t = 0; t < KS; t++) {
            float ut = u[t];
            o0 += ut*rb[t];   o1 += ut*rb[t+4];
            o2 += ut*rb[t+8]; o3 += ut*rb[t+12];
        }
    } else {
        #pragma unroll
        for (int m = 0; m < 4; m++) {
            int j = 2 + 16*g + 4*m;
            float s = 0.f;
            #pragma unroll
            for (int t = 0; t < KS; t++) {
                int jj = j - KH + t;
                if (jj >= 0 && jj < HWD) s += u[t] * row[jj];
            }
            if (m == 0) o0 = s; else if (m == 1) o1 = s; else if (m == 2) o2 = s; else o3 = s;
        }
    }
    float4* op = (float4*)(d_tmp_spec + ((size_t)(b*NCB + c)*HWD + i)*128 + 4*g);
    *op = make_float4(o0, o1, o2, o3);
}

__global__ void k_spec_v(const float* __restrict__ labels, const float* __restrict__ mask) {
    __shared__ double sd[256];
    int idx = blockIdx.x*256 + threadIdx.x;   // NB*NCB*32*128
    double num = 0.0, den = 0.0;
    if (idx < NB*NCB*32*128) {
        int bb = idx & 127;
        int g  = (idx >> 7) & 31;
        int c  = (idx >> 12) & 7;
        int b  =  idx >> 15;
        int j = 2 + 4*bb;
        const float* u = d_u + c*KS;
        const float* col = d_tmp_spec + (size_t)(b*NCB + c)*HWD*128 + bb;
        float x[4] = {0.f, 0.f, 0.f, 0.f};
        if (g >= 2 && g <= 29) {
            const float* cp = col + (size_t)(16*g - 18)*128;
            float rb[53];
            #pragma unroll
            for (int t = 0; t < 53; t++) rb[t] = cp[(size_t)t*128];
            #pragma unroll
            for (int t = 0; t < KS; t++) {
                float ut = u[t];
                x[0] += ut*rb[t];   x[1] += ut*rb[t+4];
                x[2] += ut*rb[t+8]; x[3] += ut*rb[t+12];
            }
        } else {
            #pragma unroll
            for (int m = 0; m < 4; m++) {
                int i = 2 + 16*g + 4*m;
                float s = 0.f;
                #pragma unroll
                for (int t = 0; t < KS; t++) {
                    int ii = i - KH + t;
                    if (ii >= 0 && ii < HWD) s += u[t] * col[(size_t)ii*128];
                }
                x[m] = s;
            }
        }
        #pragma unroll
        for (int m = 0; m < 4; m++) {
            int i = 2 + 16*g + 4*m;
            float y  = labels[((size_t)(b*9 + c)*HWD + i)*HWD + j];
            float mm = mask[((size_t)c*HWD + i)*HWD + j];
            num += (double)(mm * fabsf(x[m] - y));
            den += (double)mm;
        }
    }
    int t = threadIdx.x;
    sd[t] = num; __syncthreads();
    for (int s = 128; s > 0; s >>= 1) { if (t < s) sd[t] += sd[t+s]; __syncthreads(); }
    double rnum = sd[0]; __syncthreads();
    sd[t] = den; __syncthreads();
    for (int s = 128; s > 0; s >>= 1) { if (t < s) sd[t] += sd[t+s]; __syncthreads(); }
    if (t == 0) { atomicAdd(&g_acc[0], rnum); atomicAdd(&g_acc[1], sd[0]); }
}

// ---------------- pan low-pass (edge padded), 4 outputs/thread ----------------
__global__ void k_pan_row(const float* __restrict__ inp) {
    int idx = blockIdx.x*256 + threadIdx.x;   // NB*512*128
    if (idx >= NB*HWD*128) return;
    int jg = idx & 127;
    int i  = (idx >> 7) & 511;
    int b  =  idx >> 16;
    int j0 = 4*jg;
    const float* row = inp + ((size_t)(b*9 + 8)*HWD + i)*HWD;
    const float* u = d_u;
    float o0=0.f, o1=0.f, o2=0.f, o3=0.f;
    if (j0 >= KH && j0 + 3 + KH < HWD) {
        const float* rp = row + j0 - KH;   // 16B aligned (j0-20 ≡ 0 mod 4)
        float rb[44];
        #pragma unroll
        for (int t = 0; t < 11; t++) {
            float4 v = ((const float4*)rp)[t];
            rb[4*t] = v.x; rb[4*t+1] = v.y; rb[4*t+2] = v.z; rb[4*t+3] = v.w;
        }
        #pragma unroll
        for (int t = 0; t < KS; t++) {
            float ut = u[t];
            o0 += ut*rb[t];   o1 += ut*rb[t+1];
            o2 += ut*rb[t+2]; o3 += ut*rb[t+3];
        }
    } else {
        #pragma unroll
        for (int m = 0; m < 4; m++) {
            int j = j0 + m;
            float s = 0.f;
            #pragma unroll
            for (int t = 0; t < KS; t++) {
                int jj = j - KH + t;
                jj = jj < 0 ? 0 : (jj > HWD-1 ? HWD-1 : jj);
                s += u[t] * row[jj];
            }
            if (m == 0) o0 = s; else if (m == 1) o1 = s; else if (m == 2) o2 = s; else o3 = s;
        }
    }
    float4* op = (float4*)(d_panrow + ((size_t)b*HWD + i)*HWD + j0);
    *op = make_float4(o0, o1, o2, o3);
}

__global__ void k_pan_col() {
    int idx = blockIdx.x*256 + threadIdx.x;   // NB*128*512
    if (idx >= NB*128*HWD) return;
    int j  = idx & 511;
    int ig = (idx >> 9) & 127;
    int b  =  idx >> 16;
    int i0 = 4*ig;
    const float* u = d_u;
    const float* col = d_panrow + (size_t)b*HW2 + j;
    float o[4] = {0.f, 0.f, 0.f, 0.f};
    if (i0 >= KH && i0 + 3 + KH < HWD) {
        const float* cp = col + (size_t)(i0 - KH)*HWD;
        float rb[44];
        #pragma unroll
        for (int t = 0; t < 44; t++) rb[t] = cp[(size_t)t*HWD];
        #pragma unroll
        for (int t = 0; t < KS; t++) {
            float ut = u[t];
            o[0] += ut*rb[t];   o[1] += ut*rb[t+1];
            o[2] += ut*rb[t+2]; o[3] += ut*rb[t+3];
        }
    } else {
        #pragma unroll
        for (int m = 0; m < 4; m++) {
            int i = i0 + m;
            float s = 0.f;
            #pragma unroll
            for (int t = 0; t < KS; t++) {
                int ii = i - KH + t;
                ii = ii < 0 ? 0 : (ii > HWD-1 ? HWD-1 : ii);
                s += u[t] * col[(size_t)ii*HWD];
            }
            o[m] = s;
        }
    }
    float* op = d_panf + ((size_t)b*HWD + i0)*HWD + j;
    #pragma unroll
    for (int m = 0; m < 4; m++) op[(size_t)m*HWD] = o[m];
}

// ---------------- boxdb: da = x - box2W(x)/n (incremental vertical) ----------------
template<int W>
__global__ void k_boxdb(float* __restrict__ out, const float* __restrict__ in,
                        int inC, int chanOff, int nC) {
    constexpr int TS = 31 + 2*W;
    __shared__ float raw[TS][TS+1];
    __shared__ float hs[TS][32];
    int p = blockIdx.z;
    int b = p / nC, c = p - b*nC;
    const float* ip = in + (size_t)(b*inC + chanOff + c)*HW2;
    float* op = out + (size_t)p*HW2;
    int y0 = blockIdx.y*32, x0 = blockIdx.x*32;
    int ty0 = y0 - (W-1), tx0 = x0 - (W-1);
    int tx = threadIdx.x, ty = threadIdx.y;
    int tid = ty*32 + tx;
    for (int idx = tid; idx < TS*TS; idx += 256) {
        int r = idx / TS, q = idx - r*TS;
        int gi = ty0 + r, gj = tx0 + q;
        raw[r][q] = ((unsigned)gi < HWD && (unsigned)gj < HWD) ? ip[gi*HWD + gj] : 0.f;
    }
    __syncthreads();
    for (int r = ty; r < TS; r += 8) {
        float s = 0.f;
        #pragma unroll
        for (int q = 0; q < 2*W; q++) s += raw[r][tx + q];
        hs[r][tx] = s;
    }
    __syncthreads();
    const float invn = 1.0f / (4.0f*W*W);
    int ly0 = ty*4;
    float s = 0.f;
    #pragma unroll
    for (int r = 0; r < 2*W; r++) s += hs[ly0 + r][tx];
    #pragma unroll
    for (int k = 0; k < 4; k++) {
        int ly = ly0 + k;
        op[(y0 + ly)*HWD + x0 + tx] = raw[ly + W - 1][tx + W - 1] - s*invn;
        if (k < 3) s += hs[ly + 2*W][tx] - hs[ly][tx];
    }
}

// ---------------- boxsq: out = box2W(A*A), per-b fields ----------------
template<int W>
__global__ void k_boxsq(float* __restrict__ out, const float* __restrict__ A) {
    constexpr int TS = 31 + 2*W;
    __shared__ float raw[TS][TS+1];
    __shared__ float hs[TS][32];
    int b = blockIdx.z;
    const float* ap = A + (size_t)b*HW2;
    float* op = out + (size_t)b*HW2;
    int y0 = blockIdx.y*32, x0 = blockIdx.x*32;
    int ty0 = y0 - (W-1), tx0 = x0 - (W-1);
    int tx = threadIdx.x, ty = threadIdx.y;
    int tid = ty*32 + tx;
    for (int idx = tid; idx < TS*TS; idx += 256) {
        int r = idx / TS, q = idx - r*TS;
        int gi = ty0 + r, gj = tx0 + q;
        float v = 0.f;
        if ((unsigned)gi < HWD && (unsigned)gj < HWD) { float a = ap[gi*HWD + gj]; v = a*a; }
        raw[r][q] = v;
    }
    __syncthreads();
    for (int r = ty; r < TS; r += 8) {
        float s = 0.f;
        #pragma unroll
        for (int q = 0; q < 2*W; q++) s += raw[r][tx + q];
        hs[r][tx] = s;
    }
    __syncthreads();
    int ly0 = ty*4;
    float s = 0.f;
    #pragma unroll
    for (int r = 0; r < 2*W; r++) s += hs[ly0 + r][tx];
    #pragma unroll
    for (int k = 0; k < 4; k++) {
        int ly = ly0 + k;
        op[(y0 + ly)*HWD + x0 + tx] = s;
        if (k < 3) s += hs[ly + 2*W][tx] - hs[ly][tx];
    }
}

// ---------------- mega-fused structural kernel ----------------
__global__ void k_fuse() {
    __shared__ float sm[7520];
    __shared__ double sd[256];
    int p = blockIdx.z;
    int b = p >> 3;
    int tx = threadIdx.x, ty = threadIdx.y;
    int tid = ty*32 + tx;
    int y0 = blockIdx.y*32, x0 = blockIdx.x*32;
    int ly0 = ty*4;

    // ---- phase 1: w=8 (thr) ----
    {
        float* rawA = sm;              // [47][48]
        float* rawB = sm + 2256;       // [47][48]
        float* hsAB = sm + 4512;       // [47][32]
        float* hsBB = sm + 6016;       // [47][32]
        const float* A = d_da_pan + (size_t)b*HW2;
        const float* B = d_db_ms  + (size_t)p*HW2;
        int ty0 = y0 - 7, tx0 = x0 - 7;
        for (int idx = tid; idx < 47*47; idx += 256) {
            int r = idx / 47, q = idx - r*47;
            int gi = ty0 + r, gj = tx0 + q;
            float va = 0.f, vb = 0.f;
            if ((unsigned)gi < HWD && (unsigned)gj < HWD) {
                int o = gi*HWD + gj;
                va = A[o]; vb = B[o];
            }
            rawA[r*48 + q] = va; rawB[r*48 + q] = vb;
        }
        __syncthreads();
        for (int r = ty; r < 47; r += 8) {
            float sa = 0.f, sb = 0.f;
            #pragma unroll
            for (int q = 0; q < 16; q++) {
                float a = rawA[r*48 + tx + q], bb = rawB[r*48 + tx + q];
                sa += a*bb; sb += bb*bb;
            }
            hsAB[r*32 + tx] = sa; hsBB[r*32 + tx] = sb;
        }
        __syncthreads();
    }
    float thrv[4];
    {
        float* hsAB = sm + 4512;
        float* hsBB = sm + 6016;
        const float* SAA = d_saa_t + (size_t)b*HW2;
        float sab = 0.f, sbb = 0.f;
        #pragma unroll
        for (int r = 0; r < 16; r++) { sab += hsAB[(ly0+r)*32 + tx]; sbb += hsBB[(ly0+r)*32 + tx]; }
        #pragma unroll
        for (int k = 0; k < 4; k++) {
            int oi = y0 + ly0 + k;
            float saa = SAA[oi*HWD + x0 + tx];
            thrv[k] = 1.f - sab / (sqrtf(saa*sbb) + 1e-20f);
            if (k < 3) {
                sab += hsAB[(ly0+16+k)*32 + tx] - hsAB[(ly0+k)*32 + tx];
                sbb += hsBB[(ly0+16+k)*32 + tx] - hsBB[(ly0+k)*32 + tx];
            }
        }
    }
    __syncthreads();

    // ---- phase 2: w=2 (X) ----
    {
        float* rawC = sm;              // [35][36]
        float* rawD = sm + 1260;       // [35][36]
        const float* C = d_da_out + (size_t)p*HW2;
        const float* D = d_db_pan + (size_t)b*HW2;
        int ty0 = y0 - 1, tx0 = x0 - 1;
        for (int idx = tid; idx < 35*35; idx += 256) {
            int r = idx / 35, q = idx - r*35;
            int gi = ty0 + r, gj = tx0 + q;
            float vc = 0.f, vd = 0.f;
            if ((unsigned)gi < HWD && (unsigned)gj < HWD) {
                int o = gi*HWD + gj;
                vc = C[o]; vd = D[o];
            }
            rawC[r*36 + q] = vc; rawD[r*36 + q] = vd;
        }
        __syncthreads();
        float* hsCD = sm + 2520;       // [35][32]
        float* hsCC = sm + 3640;       // [35][32]
        for (int r = ty; r < 35; r += 8) {
            float scd = 0.f, scc = 0.f;
            #pragma unroll
            for (int q = 0; q < 4; q++) {
                float cc = rawC[r*36 + tx + q], dd = rawD[r*36 + tx + q];
                scd += cc*dd; scc += cc*cc;
            }
            hsCD[r*32 + tx] = scd; hsCC[r*32 + tx] = scc;
        }
        __syncthreads();
        const float* SBB = d_sbb_x + (size_t)b*HW2;
        float scd = 0.f, scc = 0.f;
        #pragma unroll
        for (int r = 0; r < 4; r++) { scd += hsCD[(ly0+r)*32 + tx]; scc += hsCC[(ly0+r)*32 + tx]; }
        double acc = 0.0;
        #pragma unroll
        for (int k = 0; k < 4; k++) {
            int oi = y0 + ly0 + k;
            float sbbx = SBB[oi*HWD + x0 + tx];
            float xc = scd / (sqrtf(scc*sbbx) + 1e-20f);
            xc = fmaxf(xc, -1.f);
            float X = 1.f - xc;
            if (X > thrv[k]) acc += (double)X;
            if (k < 3) {
                scd += hsCD[(ly0+4+k)*32 + tx] - hsCD[(ly0+k)*32 + tx];
                scc += hsCC[(ly0+4+k)*32 + tx] - hsCC[(ly0+k)*32 + tx];
            }
        }
        sd[tid] = acc;
    }
    __syncthreads();
    for (int s = 128; s > 0; s >>= 1) { if (tid < s) sd[tid] += sd[tid+s]; __syncthreads(); }
    if (tid == 0) atomicAdd(&g_acc[2], sd[0]);
}

__global__ void k_write(float* __restrict__ out) {
    double l_spec   = g_acc[0] / g_acc[1];
    double l_struct = g_acc[2] / (double)((size_t)NB*NCB*HW2);
    out[0] = (float)(l_spec + 0.25 * l_struct);
}

// ---------------- host launcher ----------------
extern "C" void kernel_launch(void* const* d_in, const int* in_sizes, int n_in,
                              void* d_out, int out_size) {
    const float* outputs = (const float*)d_in[0];
    const float* labels  = (const float*)d_in[1];
    const float* inp     = (const float*)d_in[2];
    const float* mtf     = (const float*)d_in[3];
    const float* mask    = (const float*)d_in[4];
    float* out = (float*)d_out;

    float *p_panf, *p_da_pan, *p_db_ms, *p_saa_t, *p_da_out, *p_db_pan, *p_sbb_x;
    cudaGetSymbolAddress((void**)&p_panf,   d_panf);
    cudaGetSymbolAddress((void**)&p_da_pan, d_da_pan);
    cudaGetSymbolAddress((void**)&p_db_ms,  d_db_ms);
    cudaGetSymbolAddress((void**)&p_saa_t,  d_saa_t);
    cudaGetSymbolAddress((void**)&p_da_out, d_da_out);
    cudaGetSymbolAddress((void**)&p_db_pan, d_db_pan);
    cudaGetSymbolAddress((void**)&p_sbb_x,  d_sbb_x);

    dim3 bt(32, 8);

    k_init<<<1, 512>>>(mtf);

    // spec branch (register-blocked, 4 outputs/thread)
    k_spec_h<<<(NB*NCB*HWD*32)/256, 256>>>(outputs);
    k_spec_v<<<(NB*NCB*32*128)/256, 256>>>(labels, mask);

    // pan low-pass (register-blocked)
    k_pan_row<<<(NB*HWD*128)/256, 256>>>(inp);
    k_pan_col<<<(NB*128*HWD)/256, 256>>>();

    // da fields
    k_boxdb<8><<<dim3(16,16,NB),     bt>>>(p_da_pan, p_panf, 1, 0, 1);
    k_boxdb<8><<<dim3(16,16,NB*NCB), bt>>>(p_db_ms,  inp,    9, 0, NCB);
    k_boxdb<2><<<dim3(16,16,NB*NCB), bt>>>(p_da_out, outputs, NCB, 0, NCB);
    k_boxdb<2><<<dim3(16,16,NB),     bt>>>(p_db_pan, labels,  9,   8, 1);

    // per-b self-correlation fields
    k_boxsq<8><<<dim3(16,16,NB), bt>>>(p_saa_t, p_da_pan);
    k_boxsq<2><<<dim3(16,16,NB), bt>>>(p_sbb_x, p_db_pan);

    // fused structural combine + reduce
    k_fuse<<<dim3(16,16,NB*NCB), bt>>>();

    k_write<<<1, 1>>>(out);
}